// round 14
// baseline (speedup 1.0000x reference)
#include <cuda_runtime.h>

// HopfieldNetwork_58823872086839 — FINAL (held; do not mutate on noise).
//
// Math: with threshold == 0 and W ~ uniform[0,8] (kept in [0,8] forever by
// the STDP clip), pot = state·W[idx] >= 0 elementwise for binary states, so
// `fired` is all-True, t0 = argmax = 0, and every asynchronous sweep writes
// an all-ones column for every neuron. The returned `states` tensor is
// identically 1.0f over all (B=64, T=8, 28, 28) elements — independent of
// the input spikes, random permutations, energy early-exit, and STDP weight
// updates (those mutate only W, which is never returned).
// => optimal kernel: constant fill of d_out with 1.0f (1.6 MB, one launch).
//
// Perf model (14 rounds, final):
//   Byte-identical binary measured 4.608 / 4.608 / 4.864 / 5.696 us at the
//   replay level; kernel-internal ncu time 3.55-3.90 us for EVERY variant
//   tried (STG.128 / STG.256 / TMA bulk / 98-784 CTAs / 1-2 stores per
//   thread). Replay duration = ~4.5 us launch floor + heavy-tailed
//   environment jitter (observed tail to 6.9). No in-kernel lever moves it;
//   the only real optimization was the algebraic collapse above (R0).
//   All post-R0 deltas, both directions, were sampling noise.

__global__ void __launch_bounds__(256, 1)
hopfield_ones(float4* __restrict__ out4, unsigned n4) {
    unsigned i = blockIdx.x * 256u + threadIdx.x;
    if (i < n4) {
        out4[i] = make_float4(1.0f, 1.0f, 1.0f, 1.0f);
    }
}

__global__ void hopfield_ones_tail(float* __restrict__ out,
                                   unsigned start, unsigned n) {
    unsigned i = start + threadIdx.x;
    if (i < n) out[i] = 1.0f;
}

extern "C" void kernel_launch(void* const* d_in, const int* in_sizes, int n_in,
                              void* d_out, int out_size) {
    (void)d_in; (void)in_sizes; (void)n_in;

    unsigned n = (unsigned)out_size;   // 401408 floats = 1,605,632 bytes
    unsigned n4 = n / 4u;              // 100352 float4 = 392 * 256 exactly
    if (n4) {
        unsigned blocks = (n4 + 255u) / 256u;   // 392 CTAs, one wave
        hopfield_ones<<<blocks, 256>>>((float4*)d_out, n4);
    }
    unsigned tail_start = n4 * 4u;
    if (tail_start < n) {              // not taken for this problem's shape
        hopfield_ones_tail<<<1, 256>>>((float*)d_out, tail_start, n);
    }
}

// round 15
// speedup vs baseline: 1.5035x; 1.5035x over previous
#include <cuda_runtime.h>

// HopfieldNetwork_58823872086839 — FINAL (terminal; held against noise).
//
// Math: with threshold == 0 and W ~ uniform[0,8] (kept in [0,8] forever by
// the STDP clip), pot = state·W[idx] >= 0 elementwise for binary states, so
// `fired` is all-True, t0 = argmax = 0, and every asynchronous sweep writes
// an all-ones column for every neuron. The returned `states` tensor is
// identically 1.0f over all (B=64, T=8, 28, 28) elements — independent of
// the input spikes, random permutations, energy early-exit, and STDP weight
// updates (those mutate only W, which is never returned). Exact algebra,
// seed-independent. => optimal kernel: constant fill of d_out with 1.0f.
//
// Perf record (15 rounds):
//   - Kernel-internal time 3.55-3.90 us for every variant (STG.128/STG.256/
//     TMA bulk/98-784 CTAs/1-2 stores per thread); analytic SM work ~0.1 us.
//   - Replay-level dur for BYTE-IDENTICAL binaries: 4.608, 4.608, 4.864,
//     5.696, 6.880 — monotone environment drift in late rounds (R14 even
//     shows kernel-internal drift to 4.54 us with elevated L1/issue on an
//     unchanged binary). Launch floor ~4.5 us + heavy-tailed machine jitter.
//   - Falsified along the way: TMA-drain theory (R2), STG.256 width theory
//     (R4), grid-granularity theory (R12 clean test). No in-kernel signal
//     exists post-R0. Best recorded: 4.544 us.

__global__ void __launch_bounds__(256, 1)
hopfield_ones(float4* __restrict__ out4, unsigned n4) {
    unsigned i = blockIdx.x * 256u + threadIdx.x;
    if (i < n4) {
        out4[i] = make_float4(1.0f, 1.0f, 1.0f, 1.0f);
    }
}

__global__ void hopfield_ones_tail(float* __restrict__ out,
                                   unsigned start, unsigned n) {
    unsigned i = start + threadIdx.x;
    if (i < n) out[i] = 1.0f;
}

extern "C" void kernel_launch(void* const* d_in, const int* in_sizes, int n_in,
                              void* d_out, int out_size) {
    (void)d_in; (void)in_sizes; (void)n_in;

    unsigned n = (unsigned)out_size;   // 401408 floats = 1,605,632 bytes
    unsigned n4 = n / 4u;              // 100352 float4 = 392 * 256 exactly
    if (n4) {
        unsigned blocks = (n4 + 255u) / 256u;   // 392 CTAs, one wave
        hopfield_ones<<<blocks, 256>>>((float4*)d_out, n4);
    }
    unsigned tail_start = n4 * 4u;
    if (tail_start < n) {              // not taken for this problem's shape
        hopfield_ones_tail<<<1, 256>>>((float*)d_out, tail_start, n);
    }
}